// round 7
// baseline (speedup 1.0000x reference)
#include <cuda_runtime.h>
#include <cstdint>
#include <math.h>

#define NN 50000
#define DD 200
#define RR 480
#define TT 4
#define EE 100000
#define SLOPE 0.22916666666666666f

// ---------------- device scratch (no allocations) ----------------
__device__ float g_h[NN * DD];
__device__ float g_hhA[NN * DD];
__device__ float g_hhB[NN * DD];
__device__ float g_ssq[NN];
__device__ float g_h0[RR * DD];
__device__ float g_Bt[5 * DD * DD + 4096];  // transposed weights + OOB pad
// int scratch: [0,RR)=rcnt [RR,2RR)=rwc [2RR,2RR+NN)=ecnt [2RR+NN,2RR+2NN)=ewc
__device__ int g_iblk[2 * RR + 2 * NN];
__device__ int g_roff[RR + 1];
__device__ int g_rlist[2 * EE];
__device__ int g_eoff[NN + 1];
__device__ int2 g_elist[EE];

// ---------------- helpers ----------------
__device__ __forceinline__ uint32_t smem_u32(const void* p) {
    uint32_t a;
    asm("{ .reg .u64 t; cvta.to.shared.u64 t, %1; cvt.u32.u64 %0, t; }" : "=r"(a) : "l"(p));
    return a;
}

#define CP16(sm_addr, gptr) \
    asm volatile("cp.async.ca.shared.global [%0], [%1], 16;" :: "r"(sm_addr), "l"(gptr))
#define CP_COMMIT() asm volatile("cp.async.commit_group;" ::: "memory")
#define CP_WAIT2()  asm volatile("cp.async.wait_group 2;" ::: "memory")

#define MMA_TF32(d, a, b0, b1)                                                    \
    asm volatile("mma.sync.aligned.m16n8k8.row.col.f32.tf32.tf32.f32 "            \
                 "{%0,%1,%2,%3}, {%4,%5,%6,%7}, {%8,%9}, {%0,%1,%2,%3};"          \
                 : "+f"((d)[0]), "+f"((d)[1]), "+f"((d)[2]), "+f"((d)[3])         \
                 : "r"((a)[0]), "r"((a)[1]), "r"((a)[2]), "r"((a)[3]),            \
                   "r"(b0), "r"(b1))

// ---------------- fused gather + RGCN GEMM ----------------
// A0[row] = (1/max(deg,1)) * sum_{e: dst=row}(hh[src_e] + h0[et_e])  (gathered to smem)
// out = rrelu(A0 @ Wn^T + hh @ Wl^T); optional row ssq -> ssqout.
// dynamic smem: [0, 27136) gathered A (128 rows, stride 212 floats);
//               [27136, +3*4032) cp.async pipe (A1 at +0, B at +1536 per stage).
#define SMA_STRIDE 212
#define SMA_FLOATS (128 * SMA_STRIDE)
#define PIPE_OFF SMA_FLOATS
#define FUSED_SMEM ((SMA_FLOATS + 3 * 4032) * 4)

__global__ void __launch_bounds__(256)
k_fused_rgcn(const float* __restrict__ hh, const float* __restrict__ Bn,
             const float* __restrict__ Bl, float* __restrict__ outp,
             float* __restrict__ ssqout) {
    extern __shared__ __align__(16) float dsm[];
    __shared__ float s_ssq[128];
    int tid = threadIdx.x, lane = tid & 31, wid = tid >> 5;
    int wr = wid >> 1, wc = wid & 1;
    int row0 = blockIdx.x * 128;
    if (tid < 128) s_ssq[tid] = 0.f;

    auto issue = [&](int c) {
        if (c < 50) {
            int base = PIPE_OFF + (c % 3) * 4032;
            if (c < 25) {
                int k0 = c * 8;
                #pragma unroll
                for (int j = tid; j < 416; j += 256) {
                    int n = j >> 1, h = j & 1;
                    CP16(smem_u32(&dsm[base + 1536 + n * 12 + h * 4]),
                         Bn + (size_t)n * DD + k0 + h * 4);
                }
            } else {
                int k0 = (c - 25) * 8;
                {
                    int r = tid >> 1, h = tid & 1;
                    int row = row0 + r;
                    if (row >= NN) row = NN - 1;
                    CP16(smem_u32(&dsm[base + r * 12 + h * 4]),
                         hh + (size_t)row * DD + k0 + h * 4);
                }
                #pragma unroll
                for (int j = tid; j < 416; j += 256) {
                    int n = j >> 1, h = j & 1;
                    CP16(smem_u32(&dsm[base + 1536 + n * 12 + h * 4]),
                         Bl + (size_t)n * DD + k0 + h * 4);
                }
            }
        }
        CP_COMMIT();
    };

    issue(0); issue(1); issue(2);

    // ---- gather phase: 8 warps x 16 rows ----
    for (int rr = 0; rr < 16; ++rr) {
        int r = wid * 16 + rr;
        int row = row0 + r;
        float4 a0 = make_float4(0.f, 0.f, 0.f, 0.f);
        float4 a1 = a0;
        int beg = 0, end = 0;
        if (row < NN) { beg = g_eoff[row]; end = g_eoff[row + 1]; }
        for (int j = beg; j < end; ++j) {
            int2 se = g_elist[j];
            const float4* hs = (const float4*)(hh + (size_t)se.x * DD);
            const float4* h0 = (const float4*)(g_h0 + (size_t)se.y * DD);
            float4 x = hs[lane], y = h0[lane];
            a0.x += x.x + y.x; a0.y += x.y + y.y;
            a0.z += x.z + y.z; a0.w += x.w + y.w;
            if (lane < 18) {
                float4 u = hs[lane + 32], v = h0[lane + 32];
                a1.x += u.x + v.x; a1.y += u.y + v.y;
                a1.z += u.z + v.z; a1.w += u.w + v.w;
            }
        }
        float nrm = 1.f / fmaxf((float)(end - beg), 1.f);
        a0.x *= nrm; a0.y *= nrm; a0.z *= nrm; a0.w *= nrm;
        *(float4*)&dsm[r * SMA_STRIDE + lane * 4] = a0;
        if (lane < 18) {
            a1.x *= nrm; a1.y *= nrm; a1.z *= nrm; a1.w *= nrm;
            *(float4*)&dsm[r * SMA_STRIDE + (lane + 32) * 4] = a1;
        }
    }

    float acc[2][13][4];
    #pragma unroll
    for (int mt = 0; mt < 2; ++mt)
        #pragma unroll
        for (int nt = 0; nt < 13; ++nt)
            #pragma unroll
            for (int q = 0; q < 4; ++q) acc[mt][nt][q] = 0.f;

    for (int c = 0; c < 50; ++c) {
        CP_WAIT2();
        __syncthreads();
        int base = PIPE_OFF + (c % 3) * 4032;
        uint32_t a[2][4];
        int rb = wr * 32 + (lane >> 2);
        int kk = lane & 3;
        if (c < 25) {
            int k0 = c * 8;
            #pragma unroll
            for (int mt = 0; mt < 2; ++mt) {
                int r = rb + mt * 16;
                a[mt][0] = __float_as_uint(dsm[r * SMA_STRIDE + k0 + kk]);
                a[mt][1] = __float_as_uint(dsm[(r + 8) * SMA_STRIDE + k0 + kk]);
                a[mt][2] = __float_as_uint(dsm[r * SMA_STRIDE + k0 + kk + 4]);
                a[mt][3] = __float_as_uint(dsm[(r + 8) * SMA_STRIDE + k0 + kk + 4]);
            }
        } else {
            #pragma unroll
            for (int mt = 0; mt < 2; ++mt) {
                int r = rb + mt * 16;
                a[mt][0] = __float_as_uint(dsm[base + r * 12 + kk]);
                a[mt][1] = __float_as_uint(dsm[base + (r + 8) * 12 + kk]);
                a[mt][2] = __float_as_uint(dsm[base + r * 12 + kk + 4]);
                a[mt][3] = __float_as_uint(dsm[base + (r + 8) * 12 + kk + 4]);
            }
        }
        int nb = wc * 104 + (lane >> 2);
        #pragma unroll
        for (int nt = 0; nt < 13; ++nt) {
            int n = nb + nt * 8;
            uint32_t b0 = __float_as_uint(dsm[base + 1536 + n * 12 + kk]);
            uint32_t b1 = __float_as_uint(dsm[base + 1536 + n * 12 + kk + 4]);
            MMA_TF32(acc[0][nt], a[0], b0, b1);
            MMA_TF32(acc[1][nt], a[1], b0, b1);
        }
        __syncthreads();
        issue(c + 3);
    }

    // ---- epilogue: rrelu + optional ssq ----
    float sq[2][2] = {{0.f, 0.f}, {0.f, 0.f}};
    #pragma unroll
    for (int mt = 0; mt < 2; ++mt) {
        int r = row0 + wr * 32 + mt * 16 + (lane >> 2);
        #pragma unroll
        for (int nt = 0; nt < 13; ++nt) {
            int col = wc * 104 + nt * 8 + (lane & 3) * 2;
            if (col >= DD) continue;
            #pragma unroll
            for (int half = 0; half < 2; ++half) {
                int row = r + half * 8;
                if (row >= NN) continue;
                float v0 = acc[mt][nt][half * 2];
                float v1 = acc[mt][nt][half * 2 + 1];
                float2 o;
                o.x = (v0 >= 0.f) ? v0 : v0 * SLOPE;
                o.y = (v1 >= 0.f) ? v1 : v1 * SLOPE;
                *(float2*)&outp[(size_t)row * DD + col] = o;
                sq[mt][half] += o.x * o.x + o.y * o.y;
            }
        }
    }
    if (ssqout != nullptr) {
        #pragma unroll
        for (int mt = 0; mt < 2; ++mt)
            #pragma unroll
            for (int half = 0; half < 2; ++half) {
                float v = sq[mt][half];
                v += __shfl_xor_sync(0xffffffffu, v, 1);
                v += __shfl_xor_sync(0xffffffffu, v, 2);
                if ((lane & 3) == 0)
                    atomicAdd(&s_ssq[wr * 32 + mt * 16 + (lane >> 2) + half * 8], v);
            }
        __syncthreads();
        if (tid < 128 && row0 + tid < NN) ssqout[row0 + tid] = s_ssq[tid];
    }
}

// ---------------- time-gate GEMM (streamed A, 3-stage) ----------------
__global__ void __launch_bounds__(256)
k_timegate(const float* __restrict__ A0, const float* __restrict__ B0g,
           const float* __restrict__ bt, const float* __restrict__ curv,
           const float* __restrict__ ssqv, float* __restrict__ hstate,
           float* __restrict__ hist) {
    __shared__ __align__(16) float sm[3 * 4032];
    int tid = threadIdx.x, lane = tid & 31, wid = tid >> 5;
    int wr = wid >> 1, wc = wid & 1;
    int row0 = blockIdx.x * 128;

    float acc[2][13][4];
    #pragma unroll
    for (int mt = 0; mt < 2; ++mt)
        #pragma unroll
        for (int nt = 0; nt < 13; ++nt)
            #pragma unroll
            for (int q = 0; q < 4; ++q) acc[mt][nt][q] = 0.f;

    auto issue = [&](int c) {
        if (c < 25) {
            int k0 = c * 8;
            int base = (c % 3) * 4032;
            {
                int r = tid >> 1, h = tid & 1;
                int row = row0 + r;
                if (row >= NN) row = NN - 1;
                CP16(smem_u32(&sm[base + r * 12 + h * 4]),
                     A0 + (size_t)row * DD + k0 + h * 4);
            }
            #pragma unroll
            for (int j = tid; j < 416; j += 256) {
                int n = j >> 1, h = j & 1;
                CP16(smem_u32(&sm[base + 1536 + n * 12 + h * 4]),
                     B0g + (size_t)n * DD + k0 + h * 4);
            }
        }
        CP_COMMIT();
    };

    issue(0); issue(1); issue(2);
    for (int c = 0; c < 25; ++c) {
        CP_WAIT2();
        __syncthreads();
        int base = (c % 3) * 4032;
        uint32_t a[2][4];
        int rb = wr * 32 + (lane >> 2);
        int kk = lane & 3;
        #pragma unroll
        for (int mt = 0; mt < 2; ++mt) {
            int r = rb + mt * 16;
            a[mt][0] = __float_as_uint(sm[base + r * 12 + kk]);
            a[mt][1] = __float_as_uint(sm[base + (r + 8) * 12 + kk]);
            a[mt][2] = __float_as_uint(sm[base + r * 12 + kk + 4]);
            a[mt][3] = __float_as_uint(sm[base + (r + 8) * 12 + kk + 4]);
        }
        int nb = wc * 104 + (lane >> 2);
        #pragma unroll
        for (int nt = 0; nt < 13; ++nt) {
            int n = nb + nt * 8;
            uint32_t b0 = __float_as_uint(sm[base + 1536 + n * 12 + kk]);
            uint32_t b1 = __float_as_uint(sm[base + 1536 + n * 12 + kk + 4]);
            MMA_TF32(acc[0][nt], a[0], b0, b1);
            MMA_TF32(acc[1][nt], a[1], b0, b1);
        }
        __syncthreads();
        issue(c + 3);
    }

    #pragma unroll
    for (int mt = 0; mt < 2; ++mt) {
        int r = row0 + wr * 32 + mt * 16 + (lane >> 2);
        #pragma unroll
        for (int nt = 0; nt < 13; ++nt) {
            int col = wc * 104 + nt * 8 + (lane & 3) * 2;
            if (col >= DD) continue;
            #pragma unroll
            for (int half = 0; half < 2; ++half) {
                int row = r + half * 8;
                if (row >= NN) continue;
                float v0 = acc[mt][nt][half * 2];
                float v1 = acc[mt][nt][half * 2 + 1];
                size_t off = (size_t)row * DD + col;
                float sc = 1.f / fmaxf(sqrtf(ssqv[row]), 1e-12f);
                float t0 = 1.f / (1.f + expf(-(v0 + bt[col])));
                float t1 = 1.f / (1.f + expf(-(v1 + bt[col + 1])));
                float2 cu = *(const float2*)&curv[off];
                float2 ho = *(const float2*)&hstate[off];
                float2 hn;
                hn.x = t0 * (cu.x * sc) + (1.f - t0) * ho.x;
                hn.y = t1 * (cu.y * sc) + (1.f - t1) * ho.y;
                *(float2*)&hstate[off] = hn;
                *(float2*)&hist[off] = hn;
            }
        }
    }
}

// ---------------- CSR builds (relation + entity) ----------------
__global__ void k_count(const int* __restrict__ dst, const int* __restrict__ et) {
    int e = blockIdx.x * blockDim.x + threadIdx.x;
    if (e < EE) {
        atomicAdd(&g_iblk[et[e]], 2);
        atomicAdd(&g_iblk[2 * RR + dst[e]], 1);
    }
}
__global__ void __launch_bounds__(512) k_rscan() {
    __shared__ int s[512];
    int tid = threadIdx.x;
    int v = (tid < RR) ? g_iblk[tid] : 0;
    s[tid] = v;
    __syncthreads();
    for (int o = 1; o < 512; o <<= 1) {
        int u = (tid >= o) ? s[tid - o] : 0;
        __syncthreads();
        s[tid] += u;
        __syncthreads();
    }
    if (tid < RR) g_roff[tid] = s[tid] - v;
    if (tid == 0) g_roff[RR] = 2 * EE;
}
__global__ void __launch_bounds__(1024) k_escan() {
    __shared__ int sT[1024];
    const int per = (NN + 1023) / 1024;  // 49
    int tid = threadIdx.x;
    int base = tid * per;
    int tot = 0;
    for (int k = 0; k < per; ++k) {
        int i = base + k;
        if (i < NN) tot += g_iblk[2 * RR + i];
    }
    sT[tid] = tot;
    __syncthreads();
    for (int o = 1; o < 1024; o <<= 1) {
        int v = (tid >= o) ? sT[tid - o] : 0;
        __syncthreads();
        sT[tid] += v;
        __syncthreads();
    }
    int run = (tid == 0) ? 0 : sT[tid - 1];
    for (int k = 0; k < per; ++k) {
        int i = base + k;
        if (i < NN) {
            g_eoff[i] = run;
            run += g_iblk[2 * RR + i];
        }
    }
    if (tid == 1023) g_eoff[NN] = EE;
}
__global__ void k_fill(const int* __restrict__ src, const int* __restrict__ dst,
                       const int* __restrict__ et) {
    int e = blockIdx.x * blockDim.x + threadIdx.x;
    if (e >= EE) return;
    int s = src[e], d_ = dst[e], r = et[e];
    int pr = g_roff[r] + atomicAdd(&g_iblk[RR + r], 2);
    g_rlist[pr] = s;
    g_rlist[pr + 1] = d_;
    int pe = g_eoff[d_] + atomicAdd(&g_iblk[2 * RR + NN + d_], 1);
    g_elist[pe] = make_int2(s, r);
}

// ---------------- GRU fused with relation-mean gather ----------------
__global__ void __launch_bounds__(256)
k_gru(const float* __restrict__ emb_rel, const float* __restrict__ W_ih,
      const float* __restrict__ W_hh, const float* __restrict__ b_ih,
      const float* __restrict__ b_hh) {
    __shared__ float sx[2 * DD];
    __shared__ float shp[DD];
    __shared__ __align__(16) float part[8 * DD];
    __shared__ float sgi[3 * DD];
    __shared__ float sgh[3 * DD];
    __shared__ float shn[DD];
    __shared__ float sred[8];
    int r = blockIdx.x, tid = threadIdx.x, lane = tid & 31, wid = tid >> 5;
    int beg = g_roff[r], end = g_roff[r + 1];

    float4 a0 = make_float4(0.f, 0.f, 0.f, 0.f);
    float4 a1 = a0;
    for (int j = beg + wid; j < end; j += 8) {
        int ent = g_rlist[j];
        const float4* hs = (const float4*)(g_h + (size_t)ent * DD);
        float4 x = hs[lane];
        a0.x += x.x; a0.y += x.y; a0.z += x.z; a0.w += x.w;
        if (lane < 18) {
            float4 u = hs[lane + 32];
            a1.x += u.x; a1.y += u.y; a1.z += u.z; a1.w += u.w;
        }
    }
    float4* pw = (float4*)(part + wid * DD);
    pw[lane] = a0;
    if (lane < 18) pw[lane + 32] = a1;

    for (int d = tid; d < DD; d += 256) {
        sx[d] = emb_rel[r * DD + d];
        shp[d] = g_h0[r * DD + d];
    }
    __syncthreads();
    float inv_cnt = 1.f / fmaxf((float)(end - beg), 1.f);
    for (int d = tid; d < DD; d += 256) {
        float s = 0.f;
        #pragma unroll
        for (int w = 0; w < 8; ++w) s += part[w * DD + d];
        sx[DD + d] = s * inv_cnt;
    }
    __syncthreads();

    for (int j = wid; j < 3 * DD; j += 8) {
        const float* wi = W_ih + (size_t)j * (2 * DD);
        float a = 0.f;
        for (int k = lane; k < 2 * DD; k += 32) a = fmaf(sx[k], wi[k], a);
        const float* wh = W_hh + (size_t)j * DD;
        float b = 0.f;
        for (int k = lane; k < DD; k += 32) b = fmaf(shp[k], wh[k], b);
        #pragma unroll
        for (int o = 16; o; o >>= 1) {
            a += __shfl_xor_sync(0xffffffffu, a, o);
            b += __shfl_xor_sync(0xffffffffu, b, o);
        }
        if (lane == 0) { sgi[j] = a + b_ih[j]; sgh[j] = b + b_hh[j]; }
    }
    __syncthreads();
    float ss = 0.f;
    for (int d = tid; d < DD; d += 256) {
        float rg = 1.f / (1.f + expf(-(sgi[d] + sgh[d])));
        float zg = 1.f / (1.f + expf(-(sgi[DD + d] + sgh[DD + d])));
        float ng = tanhf(sgi[2 * DD + d] + rg * sgh[2 * DD + d]);
        float hn = (1.f - zg) * ng + zg * shp[d];
        shn[d] = hn;
        ss += hn * hn;
    }
    #pragma unroll
    for (int o = 16; o; o >>= 1) ss += __shfl_xor_sync(0xffffffffu, ss, o);
    if (lane == 0) sred[wid] = ss;
    __syncthreads();
    if (tid == 0) {
        float t = 0.f;
        #pragma unroll
        for (int i = 0; i < 8; ++i) t += sred[i];
        sred[0] = t;
    }
    __syncthreads();
    float s = 1.f / fmaxf(sqrtf(sred[0]), 1e-12f);
    for (int d = tid; d < DD; d += 256) g_h0[r * DD + d] = shn[d] * s;
}

// ---------------- utility kernels ----------------
__global__ void k_copy(const float* __restrict__ in, float* __restrict__ out, int n) {
    int i = blockIdx.x * blockDim.x + threadIdx.x;
    if (i < n) out[i] = in[i];
}
__global__ void k_transpose_all(const float* __restrict__ Wn, const float* __restrict__ Wl,
                                const float* __restrict__ Wt, float* __restrict__ Bt) {
    int idx = blockIdx.x * blockDim.x + threadIdx.x;
    if (idx >= 5 * DD * DD) return;
    int m = idx / (DD * DD);
    int r = idx - m * (DD * DD);
    int k = r / DD, n = r - k * DD;
    const float* W;
    if (m == 4) W = Wt;
    else if (m & 1) W = Wl + (m >> 1) * DD * DD;
    else W = Wn + (m >> 1) * DD * DD;
    Bt[m * DD * DD + n * DD + k] = W[r];
}
__global__ void k_l2norm_rows(const float* __restrict__ in, float* __restrict__ out, int nrows) {
    int w = (blockIdx.x * blockDim.x + threadIdx.x) >> 5;
    int lane = threadIdx.x & 31;
    if (w >= nrows) return;
    const float* r = in + (size_t)w * DD;
    float ss = 0.f;
    for (int d = lane; d < DD; d += 32) { float v = r[d]; ss += v * v; }
    #pragma unroll
    for (int o = 16; o; o >>= 1) ss += __shfl_xor_sync(0xffffffffu, ss, o);
    float s = 1.f / fmaxf(sqrtf(ss), 1e-12f);
    float* po = out + (size_t)w * DD;
    for (int d = lane; d < DD; d += 32) po[d] = r[d] * s;
}

// ---------------- host driver ----------------
extern "C" void kernel_launch(void* const* d_in, const int* in_sizes, int n_in,
                              void* d_out, int out_size) {
    const int* src = (const int*)d_in[0];
    const int* dst = (const int*)d_in[1];
    const int* et  = (const int*)d_in[2];
    const float* dyn     = (const float*)d_in[3];
    const float* emb_rel = (const float*)d_in[4];
    const float* W_ih    = (const float*)d_in[5];
    const float* W_hh    = (const float*)d_in[6];
    const float* b_ih    = (const float*)d_in[7];
    const float* b_hh    = (const float*)d_in[8];
    const float* W_nb    = (const float*)d_in[9];
    const float* W_lp    = (const float*)d_in[10];
    const float* Wt      = (const float*)d_in[11];
    const float* bt      = (const float*)d_in[12];
    float* out = (float*)d_out;

    float *p_h, *p_hhA, *p_hhB, *p_ssq, *p_h0, *p_Bt;
    int* p_iblk;
    cudaGetSymbolAddress((void**)&p_h,    g_h);
    cudaGetSymbolAddress((void**)&p_hhA,  g_hhA);
    cudaGetSymbolAddress((void**)&p_hhB,  g_hhB);
    cudaGetSymbolAddress((void**)&p_ssq,  g_ssq);
    cudaGetSymbolAddress((void**)&p_h0,   g_h0);
    cudaGetSymbolAddress((void**)&p_Bt,   g_Bt);
    cudaGetSymbolAddress((void**)&p_iblk, g_iblk);

    cudaFuncSetAttribute(k_fused_rgcn, cudaFuncAttributeMaxDynamicSharedMemorySize,
                         FUSED_SMEM);

    const int gemm_blocks = (NN + 127) / 128;  // 391
    const int e1 = (EE + 255) / 256;

    k_transpose_all<<<(5 * DD * DD + 255) / 256, 256>>>(W_nb, W_lp, Wt, p_Bt);
    k_l2norm_rows<<<(NN * 32 + 255) / 256, 256>>>(dyn, p_h, NN);
    k_copy<<<(RR * DD + 255) / 256, 256>>>(emb_rel, p_h0, RR * DD);

    for (int t = 0; t < TT; ++t) {
        const int* s_t = src + t * EE;
        const int* d_t = dst + t * EE;
        const int* e_t = et  + t * EE;

        // CSR builds (relation + entity) and GRU
        cudaMemsetAsync(p_iblk, 0, (2 * RR + 2 * NN) * sizeof(int));
        k_count<<<e1, 256>>>(d_t, e_t);
        k_rscan<<<1, 512>>>();
        k_escan<<<1, 1024>>>();
        k_fill<<<e1, 256>>>(s_t, d_t, e_t);
        k_gru<<<RR, 256>>>(emb_rel, W_ih, W_hh, b_ih, b_hh);

        // layer 0: h -> hhA (gather fused)
        k_fused_rgcn<<<gemm_blocks, 256, FUSED_SMEM>>>(
            p_h, p_Bt + 0 * DD * DD, p_Bt + 1 * DD * DD, p_hhA, nullptr);

        // layer 1: hhA -> hhB (+ row ssq)
        k_fused_rgcn<<<gemm_blocks, 256, FUSED_SMEM>>>(
            p_hhA, p_Bt + 2 * DD * DD, p_Bt + 3 * DD * DD, p_hhB, p_ssq);

        // time gate
        k_timegate<<<gemm_blocks, 256>>>(
            p_h, p_Bt + 4 * DD * DD, bt, p_hhB, p_ssq, p_h,
            out + (size_t)t * NN * DD);
    }
}

// round 8
// speedup vs baseline: 1.2314x; 1.2314x over previous
#include <cuda_runtime.h>
#include <cstdint>
#include <math.h>

#define NN 50000
#define DD 200
#define RR 480
#define TT 4
#define EE 100000
#define SLOPE 0.22916666666666666f

// ---------------- device scratch (no allocations) ----------------
__device__ float g_h[NN * DD];
__device__ float g_hhA[NN * DD];
__device__ float g_hhB[NN * DD];
__device__ float g_agg[NN * DD];
__device__ float g_ssq[NN];
__device__ float g_h0[RR * DD];
__device__ float g_Bt[5 * DD * DD + 4096];  // transposed weights + OOB pad
// int scratch: [0,RR)=rcnt  [RR,2RR)=rwc  [2RR,2RR+NN)=deg
__device__ int g_iblk[2 * RR + NN];
__device__ int g_roff[RR + 1];
__device__ int g_rlist[2 * EE];

// ---------------- helpers ----------------
__device__ __forceinline__ uint32_t smem_u32(const void* p) {
    uint32_t a;
    asm("{ .reg .u64 t; cvta.to.shared.u64 t, %1; cvt.u32.u64 %0, t; }" : "=r"(a) : "l"(p));
    return a;
}

#define CP16(sm_addr, gptr) \
    asm volatile("cp.async.ca.shared.global [%0], [%1], 16;" :: "r"(sm_addr), "l"(gptr))
#define CP_COMMIT() asm volatile("cp.async.commit_group;" ::: "memory")
#define CP_WAIT2()  asm volatile("cp.async.wait_group 2;" ::: "memory")

#define MMA_TF32(d, a, b0, b1)                                                    \
    asm volatile("mma.sync.aligned.m16n8k8.row.col.f32.tf32.tf32.f32 "            \
                 "{%0,%1,%2,%3}, {%4,%5,%6,%7}, {%8,%9}, {%0,%1,%2,%3};"          \
                 : "+f"((d)[0]), "+f"((d)[1]), "+f"((d)[2]), "+f"((d)[3])         \
                 : "r"((a)[0]), "r"((a)[1]), "r"((a)[2]), "r"((a)[3]),            \
                   "r"(b0), "r"(b1))

__device__ __forceinline__ void red_add_v4(float* p, float4 v) {
    asm volatile("red.global.add.v4.f32 [%0], {%1, %2, %3, %4};"
                 :: "l"(p), "f"(v.x), "f"(v.y), "f"(v.z), "f"(v.w) : "memory");
}

// ---------------- fused tensor-core GEMM (mma.sync tf32, 3-stage pipe) ----------------
// acc[128,200] = sum_parts Apart @ Bpart^T; after part0: acc *= 1/max(deg,1).
// mode 0: out = rrelu(acc); optional row-ssq -> ssqout; optional zero zaggp rows.
// mode 1: tw=sigmoid(acc+bt); sc=1/max(sqrt(ssqv[row]),eps);
//         h = tw*(curv*sc) + (1-tw)*h; hist = h.
__global__ void __launch_bounds__(256)
k_mma_gemm(const float* __restrict__ A0, const float* __restrict__ A1,
           const float* __restrict__ B0g, const float* __restrict__ B1g,
           const int* __restrict__ degv, float* __restrict__ outp,
           float* __restrict__ ssqout, float* __restrict__ zaggp,
           const float* __restrict__ bt, const float* __restrict__ curv,
           const float* __restrict__ ssqv,
           float* __restrict__ hstate, float* __restrict__ hist,
           int mode, int nparts) {
    __shared__ __align__(16) float sm[3 * 4032];  // per stage: 1536 A + 2496 B
    __shared__ float s_ssq[128];
    int tid = threadIdx.x, lane = tid & 31, wid = tid >> 5;
    int wr = wid >> 1, wc = wid & 1;
    int row0 = blockIdx.x * 128;
    if (tid < 128) s_ssq[tid] = 0.f;

    float acc[2][13][4];
    #pragma unroll
    for (int mt = 0; mt < 2; ++mt)
        #pragma unroll
        for (int nt = 0; nt < 13; ++nt)
            #pragma unroll
            for (int q = 0; q < 4; ++q) acc[mt][nt][q] = 0.f;

    const int nk = nparts * 25;

    auto issue = [&](int c) {
        if (c < nk) {
            const float* A = (c < 25) ? A0 : A1;
            const float* B = (c < 25) ? B0g : B1g;
            int k0 = ((c < 25) ? c : c - 25) * 8;
            int base = (c % 3) * 4032;
            {
                int r = tid >> 1, h = tid & 1;
                int row = row0 + r;
                if (row >= NN) row = NN - 1;
                CP16(smem_u32(&sm[base + r * 12 + h * 4]),
                     A + (size_t)row * DD + k0 + h * 4);
            }
            #pragma unroll
            for (int j = tid; j < 416; j += 256) {
                int n = j >> 1, h = j & 1;
                CP16(smem_u32(&sm[base + 1536 + n * 12 + h * 4]),
                     B + (size_t)n * DD + k0 + h * 4);
            }
        }
        CP_COMMIT();
    };

    issue(0); issue(1); issue(2);
    for (int c = 0; c < nk; ++c) {
        CP_WAIT2();
        __syncthreads();
        int base = (c % 3) * 4032;
        uint32_t a[2][4];
        int rb = wr * 32 + (lane >> 2);
        int kk = lane & 3;
        #pragma unroll
        for (int mt = 0; mt < 2; ++mt) {
            int r = rb + mt * 16;
            a[mt][0] = __float_as_uint(sm[base + r * 12 + kk]);
            a[mt][1] = __float_as_uint(sm[base + (r + 8) * 12 + kk]);
            a[mt][2] = __float_as_uint(sm[base + r * 12 + kk + 4]);
            a[mt][3] = __float_as_uint(sm[base + (r + 8) * 12 + kk + 4]);
        }
        int nb = wc * 104 + (lane >> 2);
        #pragma unroll
        for (int nt = 0; nt < 13; ++nt) {
            int n = nb + nt * 8;
            uint32_t b0 = __float_as_uint(sm[base + 1536 + n * 12 + kk]);
            uint32_t b1 = __float_as_uint(sm[base + 1536 + n * 12 + kk + 4]);
            MMA_TF32(acc[0][nt], a[0], b0, b1);
            MMA_TF32(acc[1][nt], a[1], b0, b1);
        }
        // end of part 0: apply per-row 1/max(deg,1)
        if (c == 24 && nparts == 2) {
            #pragma unroll
            for (int mt = 0; mt < 2; ++mt) {
                int r = row0 + wr * 32 + mt * 16 + (lane >> 2);
                int r2 = r + 8;
                float n0 = 1.f / fmaxf((float)degv[r < NN ? r : NN - 1], 1.f);
                float n1 = 1.f / fmaxf((float)degv[r2 < NN ? r2 : NN - 1], 1.f);
                #pragma unroll
                for (int nt = 0; nt < 13; ++nt) {
                    acc[mt][nt][0] *= n0; acc[mt][nt][1] *= n0;
                    acc[mt][nt][2] *= n1; acc[mt][nt][3] *= n1;
                }
            }
        }
        __syncthreads();
        issue(c + 3);
    }

    // ---- epilogue ----
    float sq[2][2] = {{0.f, 0.f}, {0.f, 0.f}};
    #pragma unroll
    for (int mt = 0; mt < 2; ++mt) {
        int r = row0 + wr * 32 + mt * 16 + (lane >> 2);
        #pragma unroll
        for (int nt = 0; nt < 13; ++nt) {
            int col = wc * 104 + nt * 8 + (lane & 3) * 2;
            if (col >= DD) continue;
            #pragma unroll
            for (int half = 0; half < 2; ++half) {
                int row = r + half * 8;
                if (row >= NN) continue;
                float v0 = acc[mt][nt][half * 2];
                float v1 = acc[mt][nt][half * 2 + 1];
                size_t off = (size_t)row * DD + col;
                if (mode == 0) {
                    float2 o;
                    o.x = (v0 >= 0.f) ? v0 : v0 * SLOPE;
                    o.y = (v1 >= 0.f) ? v1 : v1 * SLOPE;
                    *(float2*)&outp[off] = o;
                    sq[mt][half] += o.x * o.x + o.y * o.y;
                } else {
                    float sc = 1.f / fmaxf(sqrtf(ssqv[row]), 1e-12f);
                    float t0 = 1.f / (1.f + expf(-(v0 + bt[col])));
                    float t1 = 1.f / (1.f + expf(-(v1 + bt[col + 1])));
                    float2 cu = *(const float2*)&curv[off];
                    float2 ho = *(const float2*)&hstate[off];
                    float2 hn;
                    hn.x = t0 * (cu.x * sc) + (1.f - t0) * ho.x;
                    hn.y = t1 * (cu.y * sc) + (1.f - t1) * ho.y;
                    *(float2*)&hstate[off] = hn;
                    *(float2*)&hist[off] = hn;
                }
            }
        }
    }
    if (mode == 0) {
        if (ssqout != nullptr) {
            #pragma unroll
            for (int mt = 0; mt < 2; ++mt)
                #pragma unroll
                for (int half = 0; half < 2; ++half) {
                    float v = sq[mt][half];
                    v += __shfl_xor_sync(0xffffffffu, v, 1);
                    v += __shfl_xor_sync(0xffffffffu, v, 2);
                    if ((lane & 3) == 0)
                        atomicAdd(&s_ssq[wr * 32 + mt * 16 + (lane >> 2) + half * 8], v);
                }
            __syncthreads();
            if (tid < 128 && row0 + tid < NN) ssqout[row0 + tid] = s_ssq[tid];
        }
        if (zaggp != nullptr) {
            float4 z = make_float4(0.f, 0.f, 0.f, 0.f);
            for (int i = tid; i < 128 * 50; i += 256) {
                int r = i / 50, q = i - r * 50;
                int row = row0 + r;
                if (row < NN) ((float4*)&zaggp[(size_t)row * DD])[q] = z;
            }
        }
    }
}

// ---------------- counts: relation (smem hist) + degree ----------------
__global__ void __launch_bounds__(256) k_count(const int* __restrict__ dst,
                                               const int* __restrict__ et) {
    __shared__ int hist[RR];
    for (int i = threadIdx.x; i < RR; i += 256) hist[i] = 0;
    __syncthreads();
    for (int e = blockIdx.x * blockDim.x + threadIdx.x; e < EE;
         e += gridDim.x * blockDim.x) {
        atomicAdd(&hist[et[e]], 2);
        atomicAdd(&g_iblk[2 * RR + dst[e]], 1);
    }
    __syncthreads();
    for (int i = threadIdx.x; i < RR; i += 256) {
        int c = hist[i];
        if (c) atomicAdd(&g_iblk[i], c);
    }
}

__global__ void __launch_bounds__(512) k_rscan() {
    __shared__ int s[512];
    int tid = threadIdx.x;
    int v = (tid < RR) ? g_iblk[tid] : 0;
    s[tid] = v;
    __syncthreads();
    for (int o = 1; o < 512; o <<= 1) {
        int u = (tid >= o) ? s[tid - o] : 0;
        __syncthreads();
        s[tid] += u;
        __syncthreads();
    }
    if (tid < RR) g_roff[tid] = s[tid] - v;  // exclusive
    if (tid == 0) g_roff[RR] = 2 * EE;
}

// ticketed fill: smem local ranks, one global atomic per nonzero bin per block
__global__ void __launch_bounds__(256)
k_rfill(const int* __restrict__ src, const int* __restrict__ dst,
        const int* __restrict__ et) {
    __shared__ int lh[RR];
    __shared__ int base[RR];
    for (int i = threadIdx.x; i < RR; i += 256) lh[i] = 0;
    __syncthreads();
    int e = blockIdx.x * blockDim.x + threadIdx.x;
    int s = 0, d_ = 0, r = 0, lr = 0;
    bool act = (e < EE);
    if (act) {
        s = src[e]; d_ = dst[e]; r = et[e];
        lr = atomicAdd(&lh[r], 2);
    }
    __syncthreads();
    for (int i = threadIdx.x; i < RR; i += 256) {
        int c = lh[i];
        base[i] = c ? atomicAdd(&g_iblk[RR + i], c) : 0;
    }
    __syncthreads();
    if (act) {
        int pos = g_roff[r] + base[r] + lr;
        g_rlist[pos] = s;
        g_rlist[pos + 1] = d_;
    }
}

// ---------------- GRU fused with relation-mean gather ----------------
__global__ void __launch_bounds__(256)
k_gru(const float* __restrict__ emb_rel, const float* __restrict__ W_ih,
      const float* __restrict__ W_hh, const float* __restrict__ b_ih,
      const float* __restrict__ b_hh) {
    __shared__ float sx[2 * DD];
    __shared__ float shp[DD];
    __shared__ __align__(16) float part[8 * DD];
    __shared__ float sgi[3 * DD];
    __shared__ float sgh[3 * DD];
    __shared__ float shn[DD];
    __shared__ float sred[8];
    int r = blockIdx.x, tid = threadIdx.x, lane = tid & 31, wid = tid >> 5;
    int beg = g_roff[r], end = g_roff[r + 1];

    float4 a0 = make_float4(0.f, 0.f, 0.f, 0.f);
    float4 a1 = a0;
    for (int j = beg + wid; j < end; j += 8) {
        int ent = g_rlist[j];
        const float4* hs = (const float4*)(g_h + (size_t)ent * DD);
        float4 x = hs[lane];
        a0.x += x.x; a0.y += x.y; a0.z += x.z; a0.w += x.w;
        if (lane < 18) {
            float4 u = hs[lane + 32];
            a1.x += u.x; a1.y += u.y; a1.z += u.z; a1.w += u.w;
        }
    }
    float4* pw = (float4*)(part + wid * DD);
    pw[lane] = a0;
    if (lane < 18) pw[lane + 32] = a1;

    for (int d = tid; d < DD; d += 256) {
        sx[d] = emb_rel[r * DD + d];
        shp[d] = g_h0[r * DD + d];
    }
    __syncthreads();
    float inv_cnt = 1.f / fmaxf((float)(end - beg), 1.f);
    for (int d = tid; d < DD; d += 256) {
        float s = 0.f;
        #pragma unroll
        for (int w = 0; w < 8; ++w) s += part[w * DD + d];
        sx[DD + d] = s * inv_cnt;
    }
    __syncthreads();

    for (int j = wid; j < 3 * DD; j += 8) {
        const float* wi = W_ih + (size_t)j * (2 * DD);
        float a = 0.f;
        for (int k = lane; k < 2 * DD; k += 32) a = fmaf(sx[k], wi[k], a);
        const float* wh = W_hh + (size_t)j * DD;
        float b = 0.f;
        for (int k = lane; k < DD; k += 32) b = fmaf(shp[k], wh[k], b);
        #pragma unroll
        for (int o = 16; o; o >>= 1) {
            a += __shfl_xor_sync(0xffffffffu, a, o);
            b += __shfl_xor_sync(0xffffffffu, b, o);
        }
        if (lane == 0) { sgi[j] = a + b_ih[j]; sgh[j] = b + b_hh[j]; }
    }
    __syncthreads();
    float ss = 0.f;
    for (int d = tid; d < DD; d += 256) {
        float rg = 1.f / (1.f + expf(-(sgi[d] + sgh[d])));
        float zg = 1.f / (1.f + expf(-(sgi[DD + d] + sgh[DD + d])));
        float ng = tanhf(sgi[2 * DD + d] + rg * sgh[2 * DD + d]);
        float hn = (1.f - zg) * ng + zg * shp[d];
        shn[d] = hn;
        ss += hn * hn;
    }
    #pragma unroll
    for (int o = 16; o; o >>= 1) ss += __shfl_xor_sync(0xffffffffu, ss, o);
    if (lane == 0) sred[wid] = ss;
    __syncthreads();
    if (tid == 0) {
        float t = 0.f;
        #pragma unroll
        for (int i = 0; i < 8; ++i) t += sred[i];
        sred[0] = t;
    }
    __syncthreads();
    float s = 1.f / fmaxf(sqrtf(sred[0]), 1e-12f);
    for (int d = tid; d < DD; d += 256) g_h0[r * DD + d] = shn[d] * s;
}

// ---------------- edge scatter: agg[dst] += hh[src] + h0[et] ----------------
// 25 threads per edge; each thread handles 8 floats (2 x red.v4).
__global__ void k_edge(const int* __restrict__ src, const int* __restrict__ dst,
                       const int* __restrict__ et, const float* __restrict__ hh) {
    int idx = blockIdx.x * blockDim.x + threadIdx.x;
    if (idx >= EE * 25) return;
    int e = idx / 25, q = idx - e * 25;
    int s = src[e], dn = dst[e], r = et[e];
    const float4* hs = (const float4*)(hh + (size_t)s * DD) + 2 * q;
    const float4* h0 = (const float4*)(g_h0 + (size_t)r * DD) + 2 * q;
    float4 a = hs[0], b = h0[0];
    float4 c = hs[1], d2 = h0[1];
    float* p = g_agg + (size_t)dn * DD + q * 8;
    red_add_v4(p, make_float4(a.x + b.x, a.y + b.y, a.z + b.z, a.w + b.w));
    red_add_v4(p + 4, make_float4(c.x + d2.x, c.y + d2.y, c.z + d2.z, c.w + d2.w));
}

// ---------------- utility kernels ----------------
__global__ void k_copy(const float* __restrict__ in, float* __restrict__ out, int n) {
    int i = blockIdx.x * blockDim.x + threadIdx.x;
    if (i < n) out[i] = in[i];
}
__global__ void k_transpose_all(const float* __restrict__ Wn, const float* __restrict__ Wl,
                                const float* __restrict__ Wt, float* __restrict__ Bt) {
    int idx = blockIdx.x * blockDim.x + threadIdx.x;
    if (idx >= 5 * DD * DD) return;
    int m = idx / (DD * DD);
    int r = idx - m * (DD * DD);
    int k = r / DD, n = r - k * DD;
    const float* W;
    if (m == 4) W = Wt;
    else if (m & 1) W = Wl + (m >> 1) * DD * DD;
    else W = Wn + (m >> 1) * DD * DD;
    Bt[m * DD * DD + n * DD + k] = W[r];
}
__global__ void k_l2norm_rows(const float* __restrict__ in, float* __restrict__ out, int nrows) {
    int w = (blockIdx.x * blockDim.x + threadIdx.x) >> 5;
    int lane = threadIdx.x & 31;
    if (w >= nrows) return;
    const float* r = in + (size_t)w * DD;
    float ss = 0.f;
    for (int d = lane; d < DD; d += 32) { float v = r[d]; ss += v * v; }
    #pragma unroll
    for (int o = 16; o; o >>= 1) ss += __shfl_xor_sync(0xffffffffu, ss, o);
    float s = 1.f / fmaxf(sqrtf(ss), 1e-12f);
    float* po = out + (size_t)w * DD;
    for (int d = lane; d < DD; d += 32) po[d] = r[d] * s;
}

// ---------------- host driver ----------------
extern "C" void kernel_launch(void* const* d_in, const int* in_sizes, int n_in,
                              void* d_out, int out_size) {
    const int* src = (const int*)d_in[0];
    const int* dst = (const int*)d_in[1];
    const int* et  = (const int*)d_in[2];
    const float* dyn     = (const float*)d_in[3];
    const float* emb_rel = (const float*)d_in[4];
    const float* W_ih    = (const float*)d_in[5];
    const float* W_hh    = (const float*)d_in[6];
    const float* b_ih    = (const float*)d_in[7];
    const float* b_hh    = (const float*)d_in[8];
    const float* W_nb    = (const float*)d_in[9];
    const float* W_lp    = (const float*)d_in[10];
    const float* Wt      = (const float*)d_in[11];
    const float* bt      = (const float*)d_in[12];
    float* out = (float*)d_out;

    float *p_h, *p_hhA, *p_hhB, *p_agg, *p_ssq, *p_h0, *p_Bt;
    int* p_iblk;
    cudaGetSymbolAddress((void**)&p_h,    g_h);
    cudaGetSymbolAddress((void**)&p_hhA,  g_hhA);
    cudaGetSymbolAddress((void**)&p_hhB,  g_hhB);
    cudaGetSymbolAddress((void**)&p_agg,  g_agg);
    cudaGetSymbolAddress((void**)&p_ssq,  g_ssq);
    cudaGetSymbolAddress((void**)&p_h0,   g_h0);
    cudaGetSymbolAddress((void**)&p_Bt,   g_Bt);
    cudaGetSymbolAddress((void**)&p_iblk, g_iblk);
    int* p_deg = p_iblk + 2 * RR;

    const int gemm_blocks = (NN + 127) / 128;  // 391
    const int eb = (EE * 25 + 255) / 256;      // 9766
    const int e1 = (EE + 255) / 256;

    k_transpose_all<<<(5 * DD * DD + 255) / 256, 256>>>(W_nb, W_lp, Wt, p_Bt);
    k_l2norm_rows<<<(NN * 32 + 255) / 256, 256>>>(dyn, p_h, NN);
    k_copy<<<(RR * DD + 255) / 256, 256>>>(emb_rel, p_h0, RR * DD);
    cudaMemsetAsync(p_agg, 0, (size_t)NN * DD * sizeof(float));

    for (int t = 0; t < TT; ++t) {
        const int* s_t = src + t * EE;
        const int* d_t = dst + t * EE;
        const int* e_t = et  + t * EE;

        // counts (relation + degree), CSR, GRU
        cudaMemsetAsync(p_iblk, 0, (2 * RR + NN) * sizeof(int));
        k_count<<<148, 256>>>(d_t, e_t);
        k_rscan<<<1, 512>>>();
        k_rfill<<<e1, 256>>>(s_t, d_t, e_t);
        k_gru<<<RR, 256>>>(emb_rel, W_ih, W_hh, b_ih, b_hh);

        // layer 0: h -> hhA (epilogue zeroes agg for layer 1)
        k_edge<<<eb, 256>>>(s_t, d_t, e_t, p_h);
        k_mma_gemm<<<gemm_blocks, 256>>>(
            p_agg, p_h, p_Bt + 0 * DD * DD, p_Bt + 1 * DD * DD, p_deg,
            p_hhA, nullptr, p_agg, nullptr, nullptr, nullptr, nullptr, nullptr, 0, 2);

        // layer 1: hhA -> hhB (+ row ssq; epilogue zeroes agg for next step)
        k_edge<<<eb, 256>>>(s_t, d_t, e_t, p_hhA);
        k_mma_gemm<<<gemm_blocks, 256>>>(
            p_agg, p_hhA, p_Bt + 2 * DD * DD, p_Bt + 3 * DD * DD, p_deg,
            p_hhB, p_ssq, p_agg, nullptr, nullptr, nullptr, nullptr, nullptr, 0, 2);

        // time gate: h = sigmoid(h@Wt+bt)*(hhB*rsqrt(ssq)) + (1-..)*h; hist = h
        k_mma_gemm<<<gemm_blocks, 256>>>(
            p_h, nullptr, p_Bt + 4 * DD * DD, nullptr, nullptr,
            nullptr, nullptr, nullptr, bt, p_hhB, p_ssq, p_h,
            out + (size_t)t * NN * DD, 1, 1);
    }
}